// round 1
// baseline (speedup 1.0000x reference)
#include <cuda_runtime.h>

// TreeNLLLoss: loss = sum_e edge_pot[e, 16*tc+tp] + sum_e unary[child, tc]
//              + unary[root, labels[root]];  out = -(loss - partition)
// E = 1,000,000 edges, N = 1,000,001 nodes, C = 16.

#define C 16
#define EDGES_PER_THREAD 4
#define THREADS 256

__device__ double g_acc;

__global__ void zero_kernel() { g_acc = 0.0; }

__global__ void __launch_bounds__(THREADS)
reduce_kernel(const float* __restrict__ edge_pot,
              const float* __restrict__ unary,
              const int*   __restrict__ labels,
              const int*   __restrict__ child_idx,
              const int*   __restrict__ parent_idx,
              int E)
{
    int base = (blockIdx.x * THREADS + threadIdx.x) * EDGES_PER_THREAD;

    // Level 0: stream indices (independent loads, batched for MLP)
    int c[EDGES_PER_THREAD], p[EDGES_PER_THREAD];
    bool v[EDGES_PER_THREAD];
    #pragma unroll
    for (int j = 0; j < EDGES_PER_THREAD; j++) {
        int e = base + j;
        v[j] = (e < E);
        c[j] = v[j] ? __ldg(&child_idx[e])  : 0;
        p[j] = v[j] ? __ldg(&parent_idx[e]) : 0;
    }

    // Level 1: label gathers (small array, L2-resident)
    int tc[EDGES_PER_THREAD], tp[EDGES_PER_THREAD];
    #pragma unroll
    for (int j = 0; j < EDGES_PER_THREAD; j++) {
        tc[j] = __ldg(&labels[c[j]]);
        tp[j] = __ldg(&labels[p[j]]);
    }

    // Level 2: potential gathers (DRAM-dominant)
    float ep[EDGES_PER_THREAD], cu[EDGES_PER_THREAD];
    #pragma unroll
    for (int j = 0; j < EDGES_PER_THREAD; j++) {
        int e = base + j;
        ep[j] = v[j] ? __ldg(&edge_pot[(size_t)e * (C * C) + tc[j] * C + tp[j]]) : 0.0f;
        cu[j] = v[j] ? __ldg(&unary[(size_t)c[j] * C + tc[j]]) : 0.0f;
    }

    float s = 0.0f;
    #pragma unroll
    for (int j = 0; j < EDGES_PER_THREAD; j++) s += ep[j] + cu[j];

    // warp reduce
    #pragma unroll
    for (int off = 16; off > 0; off >>= 1)
        s += __shfl_down_sync(0xffffffffu, s, off);

    __shared__ float warp_sums[THREADS / 32];
    int lane = threadIdx.x & 31;
    int wid  = threadIdx.x >> 5;
    if (lane == 0) warp_sums[wid] = s;
    __syncthreads();

    if (wid == 0) {
        float t = (lane < THREADS / 32) ? warp_sums[lane] : 0.0f;
        #pragma unroll
        for (int off = 4; off > 0; off >>= 1)
            t += __shfl_down_sync(0xffffffffu, t, off);
        if (lane == 0) atomicAdd(&g_acc, (double)t);
    }
}

__global__ void final_kernel(const float* __restrict__ unary,
                             const int*   __restrict__ labels,
                             const int*   __restrict__ root_idx,
                             const float* __restrict__ partition,
                             float* __restrict__ out)
{
    int r = root_idx[0];
    float root_unary = unary[(size_t)r * C + labels[r]];
    double loss = g_acc + (double)root_unary;
    out[0] = -(float)(loss - (double)partition[0]);
}

extern "C" void kernel_launch(void* const* d_in, const int* in_sizes, int n_in,
                              void* d_out, int out_size)
{
    const float* edge_pot   = (const float*)d_in[0];
    const float* unary      = (const float*)d_in[1];
    const int*   labels     = (const int*)d_in[2];
    const int*   child_idx  = (const int*)d_in[3];
    const int*   parent_idx = (const int*)d_in[4];
    const int*   root_idx   = (const int*)d_in[5];
    const float* partition  = (const float*)d_in[6];
    float* out = (float*)d_out;

    int E = in_sizes[3];  // child_idx element count

    zero_kernel<<<1, 1>>>();

    int per_block = THREADS * EDGES_PER_THREAD;
    int blocks = (E + per_block - 1) / per_block;
    reduce_kernel<<<blocks, THREADS>>>(edge_pot, unary, labels,
                                       child_idx, parent_idx, E);

    final_kernel<<<1, 1>>>(unary, labels, root_idx, partition, out);
}